// round 15
// baseline (speedup 1.0000x reference)
#include <cuda_runtime.h>
#include <cuda_bf16.h>
#include <cstdint>

#define NUSR 100000
#define NTXN 400000
#define NEDG 400000
#define NVOC 10000
#define HDIM 128
#define NLAY 3
#define HID2 64
#define OUTD 2
#define EPSV 1e-5f
#define NTOT (NUSR + NTXN)
#define NSM  148
#define ROWB 512            // bytes per split row: hi 256 | lo 256

// ===================== helpers =====================
__device__ __forceinline__ uint32_t smem_to_u32(const void* p) {
    uint32_t a;
    asm("{ .reg .u64 t; cvta.to.shared.u64 t, %1; cvt.u32.u64 %0, t; }" : "=r"(a) : "l"(p));
    return a;
}
__device__ __forceinline__ void split2(float x, float y, uint32_t& hi, uint32_t& lo) {
    __nv_bfloat162 h = __floats2bfloat162_rn(x, y);
    float rx = x - __bfloat162float(h.x);
    float ry = y - __bfloat162float(h.y);
    __nv_bfloat162 l = __floats2bfloat162_rn(rx, ry);
    hi = *(uint32_t*)&h;
    lo = *(uint32_t*)&l;
}
__device__ __forceinline__ float2 b2f(uint32_t v) {
    return __bfloat1622float2(*(__nv_bfloat162*)&v);
}
// physical byte offset (within a plane-row) of logical k-pair P (= k/2, 0..63)
__device__ __forceinline__ uint32_t pair_off(uint32_t P) {
    uint32_t b = P >> 3, q = P & 7;
    return b * 32 + (((q & 3) * 2 + (q >> 2)) * 4);
}
#define LDSM_X4(r0, r1, r2, r3, addr) \
    asm volatile("ldmatrix.sync.aligned.m8n8.x4.shared.b16 {%0,%1,%2,%3}, [%4];" \
                 : "=r"(r0), "=r"(r1), "=r"(r2), "=r"(r3) : "r"(addr))
#define MMA_BF16(d, a, b0, b1) \
    asm volatile("mma.sync.aligned.m16n8k16.row.col.f32.bf16.bf16.f32 " \
                 "{%0,%1,%2,%3}, {%4,%5,%6,%7}, {%8,%9}, {%0,%1,%2,%3};" \
                 : "+f"((d)[0]), "+f"((d)[1]), "+f"((d)[2]), "+f"((d)[3]) \
                 : "r"((a)[0]), "r"((a)[1]), "r"((a)[2]), "r"((a)[3]), "r"(b0), "r"(b1))

// ===================== scratch (device globals; split bf16 rows) =====================
__device__ unsigned char g_hu0[(size_t)NUSR * ROWB];
__device__ unsigned char g_hu1[(size_t)NUSR * ROWB];
__device__ unsigned char g_ht0[(size_t)NTXN * ROWB];
__device__ unsigned char g_ht1[(size_t)NTXN * ROWB];
__device__ unsigned char g_aggu[(size_t)NUSR * ROWB];
__device__ unsigned char g_aggt[(size_t)NTXN * ROWB];
__device__ unsigned char g_embu[(size_t)NVOC * ROWB];
__device__ unsigned char g_embt[(size_t)NVOC * ROWB];
__device__ int   g_cntu[NUSR];
__device__ int   g_cntt[NTXN];
__device__ int   g_startu[NUSR];
__device__ int   g_startt[NTXN];
__device__ int   g_tmpu[NUSR];
__device__ int   g_tmpt[NTXN];
__device__ int   g_permu[NEDG];
__device__ int   g_permt[NEDG];
__device__ int   g_cursor[2];
__device__ float4 g_wimg[6 * 2 * 4096];   // [6 (l,t)] x (hi 64KB + lo 64KB)
__device__ float4 g_w1img[2048];          // W1 hi 16KB + lo 16KB

// ===================== CSR build kernels =====================
__global__ void zero_i(int* __restrict__ p, int n) {
    int i = blockIdx.x * blockDim.x + threadIdx.x;
    if (i < n) p[i] = 0;
}
__global__ void count_deg(const int* __restrict__ dst, int* __restrict__ cnt, int n) {
    int i = blockIdx.x * blockDim.x + threadIdx.x;
    if (i < n) atomicAdd(&cnt[__ldg(dst + i)], 1);
}
__global__ void assign_off(const int* __restrict__ cnt, int* __restrict__ start,
                           int* __restrict__ tmp, int* cursor, int n) {
    __shared__ int wsum[8];
    __shared__ int sbase;
    int i = blockIdx.x * 256 + threadIdx.x;
    int lane = threadIdx.x & 31, w = threadIdx.x >> 5;
    int c = (i < n) ? __ldg(cnt + i) : 0;
    int pre = c;
    #pragma unroll
    for (int o = 1; o < 32; o <<= 1) {
        int u = __shfl_up_sync(0xffffffffu, pre, o);
        if (lane >= o) pre += u;
    }
    if (lane == 31) wsum[w] = pre;
    __syncthreads();
    if (threadIdx.x == 0) {
        int s = 0;
        #pragma unroll
        for (int j = 0; j < 8; j++) { int t = wsum[j]; wsum[j] = s; s += t; }
        sbase = atomicAdd(cursor, s);
    }
    __syncthreads();
    int off = sbase + wsum[w] + pre - c;
    if (i < n) { start[i] = off; tmp[i] = off; }
}
__global__ void fill_perm(const int* __restrict__ src, const int* __restrict__ dst,
                          int* __restrict__ tmp, int* __restrict__ perm, int n) {
    int i = blockIdx.x * blockDim.x + threadIdx.x;
    if (i < n) {
        int d = __ldg(dst + i);
        int slot = atomicAdd(&tmp[d], 1);
        perm[slot] = __ldg(src + i);
    }
}

// ===================== embedding pre-split =====================
// emb (NVOC x 128 fp32) -> split rows (hi/lo bf16, interleaved pair layout)
__global__ void embprep(const float* __restrict__ emb, unsigned char* __restrict__ dst) {
    for (int e = blockIdx.x * blockDim.x + threadIdx.x; e < NVOC * 64; e += gridDim.x * blockDim.x) {
        int r = e >> 6;
        uint32_t P = e & 63;
        float2 v = __ldg((const float2*)(emb + (size_t)r * HDIM + P * 2));
        uint32_t hi, lo;
        split2(v.x, v.y, hi, lo);
        uint32_t off = (uint32_t)(r * ROWB) + pair_off(P);
        *(uint32_t*)(dst + off)       = hi;
        *(uint32_t*)(dst + off + 256) = lo;
    }
}

// ===================== aggregation: CSR gather-mean over split rows =====================
// warp per dst node; lane handles 2 uint32 (4 elements) per plane.
__global__ void agg_mean(const int* __restrict__ start, const int* __restrict__ cnt,
                         const int* __restrict__ perm,
                         const unsigned char* __restrict__ feat, const int* __restrict__ srcidx,
                         unsigned char* __restrict__ agg, int n) {
    int t = blockIdx.x * blockDim.x + threadIdx.x;
    int d = t >> 5, lane = t & 31;
    if (d >= n) return;
    int s = __ldg(start + d), c = __ldg(cnt + d);
    float a0 = 0.f, a1 = 0.f, a2 = 0.f, a3 = 0.f;
    int loff = lane * 8;
    for (int j = 0; j < c; j++) {
        int src = __ldg(perm + s + j);
        if (srcidx) src = __ldg(srcidx + src);
        const unsigned char* rp = feat + (size_t)src * ROWB + loff;
        uint2 vh = __ldg((const uint2*)rp);
        uint2 vl = __ldg((const uint2*)(rp + 256));
        float2 h0 = b2f(vh.x), h1 = b2f(vh.y), l0 = b2f(vl.x), l1 = b2f(vl.y);
        a0 += h0.x + l0.x; a1 += h0.y + l0.y;
        a2 += h1.x + l1.x; a3 += h1.y + l1.y;
    }
    float sc = 1.f / (float)(c > 1 ? c : 1);
    a0 *= sc; a1 *= sc; a2 *= sc; a3 *= sc;
    uint32_t h0u, l0u, h1u, l1u;
    split2(a0, a1, h0u, l0u);
    split2(a2, a3, h1u, l1u);
    unsigned char* op = agg + (size_t)d * ROWB + loff;
    *(uint2*)op         = make_uint2(h0u, h1u);
    *(uint2*)(op + 256) = make_uint2(l0u, l1u);
}

// ===================== weight prep =====================
__global__ void wprep(const float* __restrict__ Wl, const float* __restrict__ Wr) {
    int lt = blockIdx.x;
    const float* wl = Wl + (size_t)lt * HDIM * HDIM;
    const float* wr = Wr + (size_t)lt * HDIM * HDIM;
    unsigned char* dhi = (unsigned char*)g_wimg + (size_t)lt * 131072;
    unsigned char* dlo = dhi + 65536;
    for (int e = threadIdx.x; e < 256 * 128; e += blockDim.x) {
        int k = e >> 7, n = e & 127;
        float v = (k < 128) ? __ldg(wl + k * HDIM + n) : __ldg(wr + (k - 128) * HDIM + n);
        __nv_bfloat16 hi = __float2bfloat16_rn(v);
        __nv_bfloat16 lo = __float2bfloat16_rn(v - __bfloat162float(hi));
        uint32_t off = (uint32_t)n * 512 + (((uint32_t)k * 2) ^ (uint32_t)((n & 7) * 16));
        *(__nv_bfloat16*)(dhi + off) = hi;
        *(__nv_bfloat16*)(dlo + off) = lo;
    }
}
__global__ void w1prep(const float* __restrict__ W1) {
    unsigned char* dhi = (unsigned char*)g_w1img;
    unsigned char* dlo = dhi + 16384;
    for (int e = blockIdx.x * blockDim.x + threadIdx.x; e < 128 * 64; e += gridDim.x * blockDim.x) {
        int k = e >> 6, n = e & 63;
        float v = __ldg(W1 + k * HID2 + n);
        __nv_bfloat16 hi = __float2bfloat16_rn(v);
        __nv_bfloat16 lo = __float2bfloat16_rn(v - __bfloat162float(hi));
        uint32_t off = (uint32_t)n * 256 + (((uint32_t)k * 2) ^ (uint32_t)((n & 7) * 16));
        *(__nv_bfloat16*)(dhi + off) = hi;
        *(__nv_bfloat16*)(dlo + off) = lo;
    }
}

// ===================== persistent tensor-core fused dual GEMM + bias + BN + ReLU ==========
// A operands pre-split (no split2 in k-loop). out written in split format.
#define SMB_SCL 0
#define SMB_SFT 512
#define SMB_BHI 1024
#define SMB_BLO (1024 + 65536)
#define SMB_TOT (1024 + 131072)

__global__ __launch_bounds__(256, 1) void gemm_mma(
    const unsigned char* __restrict__ A1,
    const unsigned char* __restrict__ self, const int* __restrict__ selfidx,
    const float4* __restrict__ wimg,
    const float* __restrict__ bias,
    const float* __restrict__ gma, const float* __restrict__ bta,
    const float* __restrict__ mu,  const float* __restrict__ var,
    unsigned char* __restrict__ out, int M)
{
    extern __shared__ char smem[];
    uint32_t sb = smem_to_u32(smem);
    const int tid  = threadIdx.x;
    const int lane = tid & 31;
    const int wid  = tid >> 5;

    {
        float4* bs = (float4*)(smem + SMB_BHI);
        #pragma unroll 4
        for (int i = tid; i < 8192; i += 256) bs[i] = __ldg(wimg + i);
    }
    if (tid < HDIM) {
        float rs = rsqrtf(__ldg(var + tid) + EPSV) * __ldg(gma + tid);
        ((float*)(smem + SMB_SCL))[tid] = rs;
        ((float*)(smem + SMB_SFT))[tid] = __ldg(bta + tid) + (__ldg(bias + tid) - __ldg(mu + tid)) * rs;
    }
    __syncthreads();

    const int warp_m = wid & 3;
    const int warp_n = wid >> 2;
    const int n0 = warp_n * 64;
    const int g  = lane >> 2;
    const int tg = lane & 3;

    const int n_off  = (lane & 7) + ((lane >> 4) << 3);
    const int k_half = (lane & 8) << 1;
    const uint32_t xorv = (uint32_t)((n_off & 7) << 4);
    uint32_t brow_hi[4], brow_lo[4];
    #pragma unroll
    for (int np = 0; np < 4; np++) {
        uint32_t nrow = (uint32_t)(n0 + np * 16 + n_off) * 512u;
        brow_hi[np] = sb + SMB_BHI + nrow;
        brow_lo[np] = sb + SMB_BLO + nrow;
    }
    const float* scl = (const float*)(smem + SMB_SCL);
    const float* sft = (const float*)(smem + SMB_SFT);

    const int ntiles = (M + 127) >> 7;
    for (int tile = blockIdx.x; tile < ntiles; tile += gridDim.x) {
        const int m0 = tile * 128 + warp_m * 32;

        // split-row base pointers for 4 rows (A1 tile k<128; self tile k>=128)
        const unsigned char* pa1[4];
        const unsigned char* pa2[4];
        #pragma unroll
        for (int i = 0; i < 4; i++) {
            int r = m0 + g + i * 8;
            r = r < M ? r : (M - 1);
            pa1[i] = A1 + (size_t)r * ROWB;
            int sr = selfidx ? __ldg(selfidx + r) : r;
            pa2[i] = self + (size_t)sr * ROWB;
        }

        float acc[2][8][4];
        #pragma unroll
        for (int mt = 0; mt < 2; mt++)
            #pragma unroll
            for (int nt = 0; nt < 8; nt++)
                #pragma unroll
                for (int q = 0; q < 4; q++) acc[mt][nt][q] = 0.f;

        // ---- software-pipelined k-loop (pre-split: 8 LDG.64 per kk, no ALU) ----
        uint2 xh[4], xl[4];
        {
            int off = tg * 8;
            #pragma unroll
            for (int i = 0; i < 4; i++) {
                xh[i] = __ldg((const uint2*)(pa1[i] + off));
                xl[i] = __ldg((const uint2*)(pa1[i] + off + 256));
            }
        }
        #pragma unroll 2
        for (int kk = 0; kk < 16; kk++) {
            // assemble fragments from current block
            uint32_t ah[2][4], al[2][4];
            #pragma unroll
            for (int mt = 0; mt < 2; mt++) {
                int i0 = mt * 2, i1 = mt * 2 + 1;
                ah[mt][0] = xh[i0].x; ah[mt][1] = xh[i1].x;
                ah[mt][2] = xh[i0].y; ah[mt][3] = xh[i1].y;
                al[mt][0] = xl[i0].x; al[mt][1] = xl[i1].x;
                al[mt][2] = xl[i0].y; al[mt][3] = xl[i1].y;
            }
            // prefetch next block
            uint2 nh[4], nl[4];
            if (kk < 15) {
                int kn = kk + 1;
                int off = (kn & 7) * 32 + tg * 8;
                if (kn < 8) {
                    #pragma unroll
                    for (int i = 0; i < 4; i++) {
                        nh[i] = __ldg((const uint2*)(pa1[i] + off));
                        nl[i] = __ldg((const uint2*)(pa1[i] + off + 256));
                    }
                } else {
                    #pragma unroll
                    for (int i = 0; i < 4; i++) {
                        nh[i] = __ldg((const uint2*)(pa2[i] + off));
                        nl[i] = __ldg((const uint2*)(pa2[i] + off + 256));
                    }
                }
            }
            // B fragments + 3-chain MMA
            uint32_t kterm = (uint32_t)((kk * 32 + k_half)) ^ xorv;
            #pragma unroll
            for (int np = 0; np < 4; np++) {
                uint32_t bh0, bh1, bh2, bh3, bl0, bl1, bl2, bl3;
                LDSM_X4(bh0, bh1, bh2, bh3, brow_hi[np] + kterm);
                LDSM_X4(bl0, bl1, bl2, bl3, brow_lo[np] + kterm);
                #pragma unroll
                for (int mt = 0; mt < 2; mt++) {
                    MMA_BF16(acc[mt][2 * np],     ah[mt], bh0, bh1);
                    MMA_BF16(acc[mt][2 * np],     al[mt], bh0, bh1);
                    MMA_BF16(acc[mt][2 * np],     ah[mt], bl0, bl1);
                    MMA_BF16(acc[mt][2 * np + 1], ah[mt], bh2, bh3);
                    MMA_BF16(acc[mt][2 * np + 1], al[mt], bh2, bh3);
                    MMA_BF16(acc[mt][2 * np + 1], ah[mt], bl2, bl3);
                }
            }
            if (kk < 15) {
                #pragma unroll
                for (int i = 0; i < 4; i++) { xh[i] = nh[i]; xl[i] = nl[i]; }
            }
        }

        // ---- epilogue: BN+ReLU, split to hi/lo, store in split layout ----
        #pragma unroll
        for (int mt = 0; mt < 2; mt++) {
            int r_lo = m0 + mt * 16 + g;
            int r_hi = r_lo + 8;
            #pragma unroll
            for (int nt = 0; nt < 8; nt++) {
                int c = n0 + nt * 8 + tg * 2;
                float s0 = scl[c], s1 = scl[c + 1];
                float f0 = sft[c], f1 = sft[c + 1];
                uint32_t po = pair_off((uint32_t)(c >> 1));
                if (r_lo < M) {
                    float ox = fmaxf(fmaf(acc[mt][nt][0], s0, f0), 0.f);
                    float oy = fmaxf(fmaf(acc[mt][nt][1], s1, f1), 0.f);
                    uint32_t hi, lo;
                    split2(ox, oy, hi, lo);
                    unsigned char* op = out + (size_t)r_lo * ROWB + po;
                    *(uint32_t*)op         = hi;
                    *(uint32_t*)(op + 256) = lo;
                }
                if (r_hi < M) {
                    float ox = fmaxf(fmaf(acc[mt][nt][2], s0, f0), 0.f);
                    float oy = fmaxf(fmaf(acc[mt][nt][3], s1, f1), 0.f);
                    uint32_t hi, lo;
                    split2(ox, oy, hi, lo);
                    unsigned char* op = out + (size_t)r_hi * ROWB + po;
                    *(uint32_t*)op         = hi;
                    *(uint32_t*)(op + 256) = lo;
                }
            }
        }
    }
}

// ===================== tensor-core MLP head (split-format input) =====================
__global__ __launch_bounds__(256, 2) void mlp_mma(
    const unsigned char* __restrict__ hu, const unsigned char* __restrict__ ht,
    const float4* __restrict__ w1img,
    const float* __restrict__ b1, const float* __restrict__ W2, const float* __restrict__ b2,
    float* __restrict__ out)
{
    __shared__ float4 sB[2048];
    __shared__ float sb1[HID2];
    __shared__ float sW2[HID2 * OUTD];
    __shared__ float sb2[OUTD];
    for (int i = threadIdx.x; i < 2048; i += 256) sB[i] = __ldg(w1img + i);
    if (threadIdx.x < HID2) sb1[threadIdx.x] = __ldg(b1 + threadIdx.x);
    if (threadIdx.x < HID2 * OUTD) sW2[threadIdx.x] = __ldg(W2 + threadIdx.x);
    if (threadIdx.x < OUTD) sb2[threadIdx.x] = __ldg(b2 + threadIdx.x);
    __syncthreads();

    const int lane = threadIdx.x & 31;
    const int wid  = threadIdx.x >> 5;
    const int m0 = blockIdx.x * 256 + wid * 32;
    const int g  = lane >> 2;
    const int tg = lane & 3;

    const unsigned char* pa[4];
    #pragma unroll
    for (int i = 0; i < 4; i++) {
        int r = m0 + g + i * 8;
        r = r < NTOT ? r : (NTOT - 1);
        pa[i] = (r < NUSR) ? hu + (size_t)r * ROWB : ht + (size_t)(r - NUSR) * ROWB;
    }

    const int n_off  = (lane & 7) + ((lane >> 4) << 3);
    const int k_half = (lane & 8) << 1;
    const uint32_t xorv = (uint32_t)((n_off & 7) << 4);
    uint32_t sbu = smem_to_u32(sB);
    uint32_t brow_hi[4], brow_lo[4];
    #pragma unroll
    for (int np = 0; np < 4; np++) {
        uint32_t nrow = (uint32_t)(np * 16 + n_off) * 256u;
        brow_hi[np] = sbu + nrow;
        brow_lo[np] = sbu + 16384u + nrow;
    }

    float acc[2][8][4];
    #pragma unroll
    for (int mt = 0; mt < 2; mt++)
        #pragma unroll
        for (int nt = 0; nt < 8; nt++)
            #pragma unroll
            for (int q = 0; q < 4; q++) acc[mt][nt][q] = 0.f;

    #pragma unroll 2
    for (int kk = 0; kk < 8; kk++) {
        int off = kk * 32 + tg * 8;
        uint2 xh[4], xl[4];
        #pragma unroll
        for (int i = 0; i < 4; i++) {
            xh[i] = __ldg((const uint2*)(pa[i] + off));
            xl[i] = __ldg((const uint2*)(pa[i] + off + 256));
        }
        uint32_t ah[2][4], al[2][4];
        #pragma unroll
        for (int mt = 0; mt < 2; mt++) {
            int i0 = mt * 2, i1 = mt * 2 + 1;
            ah[mt][0] = xh[i0].x; ah[mt][1] = xh[i1].x;
            ah[mt][2] = xh[i0].y; ah[mt][3] = xh[i1].y;
            al[mt][0] = xl[i0].x; al[mt][1] = xl[i1].x;
            al[mt][2] = xl[i0].y; al[mt][3] = xl[i1].y;
        }
        uint32_t kterm = (uint32_t)((kk * 32 + k_half)) ^ xorv;
        #pragma unroll
        for (int np = 0; np < 4; np++) {
            uint32_t bh0, bh1, bh2, bh3, bl0, bl1, bl2, bl3;
            LDSM_X4(bh0, bh1, bh2, bh3, brow_hi[np] + kterm);
            LDSM_X4(bl0, bl1, bl2, bl3, brow_lo[np] + kterm);
            #pragma unroll
            for (int mt = 0; mt < 2; mt++) {
                MMA_BF16(acc[mt][2 * np],     ah[mt], bh0, bh1);
                MMA_BF16(acc[mt][2 * np],     al[mt], bh0, bh1);
                MMA_BF16(acc[mt][2 * np],     ah[mt], bl0, bl1);
                MMA_BF16(acc[mt][2 * np + 1], ah[mt], bh2, bh3);
                MMA_BF16(acc[mt][2 * np + 1], al[mt], bh2, bh3);
                MMA_BF16(acc[mt][2 * np + 1], ah[mt], bl2, bl3);
            }
        }
    }

    #pragma unroll
    for (int mt = 0; mt < 2; mt++) {
        #pragma unroll
        for (int half = 0; half < 2; half++) {
            int row = m0 + mt * 16 + g + half * 8;
            float oA = 0.f, oB = 0.f;
            #pragma unroll
            for (int nt = 0; nt < 8; nt++) {
                int c = nt * 8 + tg * 2;
                float h0 = fmaxf(acc[mt][nt][half * 2 + 0] + sb1[c],     0.f);
                float h1 = fmaxf(acc[mt][nt][half * 2 + 1] + sb1[c + 1], 0.f);
                oA = fmaf(h0, sW2[c * OUTD],     fmaf(h1, sW2[(c + 1) * OUTD],     oA));
                oB = fmaf(h0, sW2[c * OUTD + 1], fmaf(h1, sW2[(c + 1) * OUTD + 1], oB));
            }
            oA += __shfl_xor_sync(0xffffffffu, oA, 1);
            oA += __shfl_xor_sync(0xffffffffu, oA, 2);
            oB += __shfl_xor_sync(0xffffffffu, oB, 1);
            oB += __shfl_xor_sync(0xffffffffu, oB, 2);
            if (tg == 0 && row < NTOT) {
                out[(size_t)row * OUTD + 0] = oA + sb2[0];
                out[(size_t)row * OUTD + 1] = oB + sb2[1];
            }
        }
    }
}

// ===================== launcher =====================
extern "C" void kernel_launch(void* const* d_in, const int* in_sizes, int n_in,
                              void* d_out, int out_size) {
    (void)in_sizes; (void)n_in; (void)out_size;
    const int*   x_user  = (const int*)  d_in[0];
    const int*   x_txn   = (const int*)  d_in[1];
    const int*   ei0_src = (const int*)  d_in[2];
    const int*   ei0_dst = (const int*)  d_in[3];
    const int*   ei1_src = (const int*)  d_in[4];
    const int*   ei1_dst = (const int*)  d_in[5];
    const float* emb_u   = (const float*)d_in[6];
    const float* emb_t   = (const float*)d_in[7];
    const float* Wl      = (const float*)d_in[8];
    const float* bl      = (const float*)d_in[9];
    const float* Wr      = (const float*)d_in[10];
    const float* bn_g    = (const float*)d_in[11];
    const float* bn_b    = (const float*)d_in[12];
    const float* bn_m    = (const float*)d_in[13];
    const float* bn_v    = (const float*)d_in[14];
    const float* W1      = (const float*)d_in[15];
    const float* b1      = (const float*)d_in[16];
    const float* W2      = (const float*)d_in[17];
    const float* b2      = (const float*)d_in[18];
    float* out = (float*)d_out;

    unsigned char *hu[2], *ht[2], *aggu, *aggt, *embuS, *embtS;
    int *cntu, *cntt, *startu, *startt, *tmpu, *tmpt, *permu, *permt, *cursor;
    float4 *wimg, *w1img;
    cudaGetSymbolAddress((void**)&hu[0],  g_hu0);
    cudaGetSymbolAddress((void**)&hu[1],  g_hu1);
    cudaGetSymbolAddress((void**)&ht[0],  g_ht0);
    cudaGetSymbolAddress((void**)&ht[1],  g_ht1);
    cudaGetSymbolAddress((void**)&aggu,   g_aggu);
    cudaGetSymbolAddress((void**)&aggt,   g_aggt);
    cudaGetSymbolAddress((void**)&embuS,  g_embu);
    cudaGetSymbolAddress((void**)&embtS,  g_embt);
    cudaGetSymbolAddress((void**)&cntu,   g_cntu);
    cudaGetSymbolAddress((void**)&cntt,   g_cntt);
    cudaGetSymbolAddress((void**)&startu, g_startu);
    cudaGetSymbolAddress((void**)&startt, g_startt);
    cudaGetSymbolAddress((void**)&tmpu,   g_tmpu);
    cudaGetSymbolAddress((void**)&tmpt,   g_tmpt);
    cudaGetSymbolAddress((void**)&permu,  g_permu);
    cudaGetSymbolAddress((void**)&permt,  g_permt);
    cudaGetSymbolAddress((void**)&cursor, g_cursor);
    cudaGetSymbolAddress((void**)&wimg,   g_wimg);
    cudaGetSymbolAddress((void**)&w1img,  g_w1img);

    cudaFuncSetAttribute(gemm_mma, cudaFuncAttributeMaxDynamicSharedMemorySize, SMB_TOT);

    // 0) bake weight + embedding images
    wprep<<<6, 256>>>(Wl, Wr);
    w1prep<<<8, 256>>>(W1);
    embprep<<<640, 256>>>(emb_u, embuS);
    embprep<<<640, 256>>>(emb_t, embtS);

    // 1) CSR build (layer-invariant)
    zero_i<<<(NTXN + 255) / 256, 256>>>(cntt, NTXN);
    zero_i<<<(NUSR + 255) / 256, 256>>>(cntu, NUSR);
    zero_i<<<1, 32>>>(cursor, 2);
    count_deg<<<(NEDG + 255) / 256, 256>>>(ei0_dst, cntt, NEDG);
    count_deg<<<(NEDG + 255) / 256, 256>>>(ei1_dst, cntu, NEDG);
    assign_off<<<(NTXN + 255) / 256, 256>>>(cntt, startt, tmpt, cursor + 0, NTXN);
    assign_off<<<(NUSR + 255) / 256, 256>>>(cntu, startu, tmpu, cursor + 1, NUSR);
    fill_perm<<<(NEDG + 255) / 256, 256>>>(ei0_src, ei0_dst, tmpt, permt, NEDG);
    fill_perm<<<(NEDG + 255) / 256, 256>>>(ei1_src, ei1_dst, tmpu, permu, NEDG);

    // 2) layers (double-buffered split activations; layer 0 via pre-split emb + index)
    for (int l = 0; l < NLAY; l++) {
        const unsigned char* su  = (l == 0) ? embuS : hu[(l + 1) & 1];
        const unsigned char* st_ = (l == 0) ? embtS : ht[(l + 1) & 1];
        const int* ixu = (l == 0) ? x_user : nullptr;
        const int* ixt = (l == 0) ? x_txn  : nullptr;
        unsigned char* out_t = ht[l & 1];
        unsigned char* out_u = hu[l & 1];

        agg_mean<<<(NTXN * 32 + 255) / 256, 256>>>(startt, cntt, permt, su,  ixu, aggt, NTXN);
        agg_mean<<<(NUSR * 32 + 255) / 256, 256>>>(startu, cntu, permu, st_, ixt, aggu, NUSR);

        // txn nodes: weights/bias (l,0), BN (l,1)
        {
            int lt = l * 2 + 0;
            gemm_mma<<<NSM, 256, SMB_TOT>>>(
                aggt, st_, ixt,
                wimg + (size_t)lt * 8192,
                bl   + (size_t)lt * HDIM,
                bn_g + (size_t)(l * 2 + 1) * HDIM, bn_b + (size_t)(l * 2 + 1) * HDIM,
                bn_m + (size_t)(l * 2 + 1) * HDIM, bn_v + (size_t)(l * 2 + 1) * HDIM,
                out_t, NTXN);
        }
        // user nodes: weights/bias (l,1), BN (l,0)
        {
            int lt = l * 2 + 1;
            gemm_mma<<<NSM, 256, SMB_TOT>>>(
                aggu, su, ixu,
                wimg + (size_t)lt * 8192,
                bl   + (size_t)lt * HDIM,
                bn_g + (size_t)(l * 2 + 0) * HDIM, bn_b + (size_t)(l * 2 + 0) * HDIM,
                bn_m + (size_t)(l * 2 + 0) * HDIM, bn_v + (size_t)(l * 2 + 0) * HDIM,
                out_u, NUSR);
        }
    }

    // 3) MLP head (final layer wrote buffer index (NLAY-1)&1 = 0)
    mlp_mma<<<(NTOT + 255) / 256, 256>>>(hu[(NLAY - 1) & 1], ht[(NLAY - 1) & 1],
                                         w1img, b1, W2, b2, out);
}

// round 16
// speedup vs baseline: 1.0758x; 1.0758x over previous
#include <cuda_runtime.h>
#include <cuda_bf16.h>
#include <cstdint>

#define NUSR 100000
#define NTXN 400000
#define NEDG 400000
#define HDIM 128
#define NLAY 3
#define HID2 64
#define OUTD 2
#define EPSV 1e-5f
#define NTOT (NUSR + NTXN)
#define NSM  148

// ===================== helpers =====================
__device__ __forceinline__ uint32_t smem_to_u32(const void* p) {
    uint32_t a;
    asm("{ .reg .u64 t; cvta.to.shared.u64 t, %1; cvt.u32.u64 %0, t; }" : "=r"(a) : "l"(p));
    return a;
}
__device__ __forceinline__ void split2(float x, float y, uint32_t& hi, uint32_t& lo) {
    __nv_bfloat162 h = __floats2bfloat162_rn(x, y);
    float rx = x - __bfloat162float(h.x);
    float ry = y - __bfloat162float(h.y);
    __nv_bfloat162 l = __floats2bfloat162_rn(rx, ry);
    hi = *(uint32_t*)&h;
    lo = *(uint32_t*)&l;
}
#define LDSM_X4(r0, r1, r2, r3, addr) \
    asm volatile("ldmatrix.sync.aligned.m8n8.x4.shared.b16 {%0,%1,%2,%3}, [%4];" \
                 : "=r"(r0), "=r"(r1), "=r"(r2), "=r"(r3) : "r"(addr))
#define MMA_BF16(d, a, b0, b1) \
    asm volatile("mma.sync.aligned.m16n8k16.row.col.f32.bf16.bf16.f32 " \
                 "{%0,%1,%2,%3}, {%4,%5,%6,%7}, {%8,%9}, {%0,%1,%2,%3};" \
                 : "+f"((d)[0]), "+f"((d)[1]), "+f"((d)[2]), "+f"((d)[3]) \
                 : "r"((a)[0]), "r"((a)[1]), "r"((a)[2]), "r"((a)[3]), "r"(b0), "r"(b1))

// ===================== scratch (device globals) =====================
__device__ float g_hu0[(size_t)NUSR * HDIM];
__device__ float g_hu1[(size_t)NUSR * HDIM];
__device__ float g_ht0[(size_t)NTXN * HDIM];
__device__ float g_ht1[(size_t)NTXN * HDIM];
__device__ float g_aggu[(size_t)NUSR * HDIM];
__device__ float g_aggt[(size_t)NTXN * HDIM];
__device__ int   g_cntu[NUSR];
__device__ int   g_cntt[NTXN];
__device__ int   g_startu[NUSR];
__device__ int   g_startt[NTXN];
__device__ int   g_tmpu[NUSR];
__device__ int   g_tmpt[NTXN];
__device__ int   g_permu[NEDG];
__device__ int   g_permt[NEDG];
__device__ int   g_cursor[2];
__device__ float4 g_wimg[6 * 2 * 4096];   // [6 (l,t)] x (hi 64KB + lo 64KB)
__device__ float4 g_w1img[2048];          // W1 hi 16KB + lo 16KB

// ===================== CSR build kernels =====================
__global__ void zero_i(int* __restrict__ p, int n) {
    int i = blockIdx.x * blockDim.x + threadIdx.x;
    if (i < n) p[i] = 0;
}
__global__ void count_deg(const int* __restrict__ dst, int* __restrict__ cnt, int n) {
    int i = blockIdx.x * blockDim.x + threadIdx.x;
    if (i < n) atomicAdd(&cnt[__ldg(dst + i)], 1);
}
__global__ void assign_off(const int* __restrict__ cnt, int* __restrict__ start,
                           int* __restrict__ tmp, int* cursor, int n) {
    __shared__ int wsum[8];
    __shared__ int sbase;
    int i = blockIdx.x * 256 + threadIdx.x;
    int lane = threadIdx.x & 31, w = threadIdx.x >> 5;
    int c = (i < n) ? __ldg(cnt + i) : 0;
    int pre = c;
    #pragma unroll
    for (int o = 1; o < 32; o <<= 1) {
        int u = __shfl_up_sync(0xffffffffu, pre, o);
        if (lane >= o) pre += u;
    }
    if (lane == 31) wsum[w] = pre;
    __syncthreads();
    if (threadIdx.x == 0) {
        int s = 0;
        #pragma unroll
        for (int j = 0; j < 8; j++) { int t = wsum[j]; wsum[j] = s; s += t; }
        sbase = atomicAdd(cursor, s);
    }
    __syncthreads();
    int off = sbase + wsum[w] + pre - c;
    if (i < n) { start[i] = off; tmp[i] = off; }
}
__global__ void fill_perm(const int* __restrict__ src, const int* __restrict__ dst,
                          int* __restrict__ tmp, int* __restrict__ perm, int n) {
    int i = blockIdx.x * blockDim.x + threadIdx.x;
    if (i < n) {
        int d = __ldg(dst + i);
        int slot = atomicAdd(&tmp[d], 1);
        perm[slot] = __ldg(src + i);
    }
}

// ===================== merged aggregation (both node types in one launch) =====================
// warps [0, NTXN): txn dsts gather user feats; warps [NTXN, NTOT): user dsts gather txn feats.
__global__ void agg_both(
    const int* __restrict__ startt, const int* __restrict__ cntt, const int* __restrict__ permt,
    const float* __restrict__ featu, const int* __restrict__ ixu,   // user feats (+opt index)
    float* __restrict__ aggt,
    const int* __restrict__ startu, const int* __restrict__ cntu, const int* __restrict__ permu,
    const float* __restrict__ featt, const int* __restrict__ ixt,   // txn feats (+opt index)
    float* __restrict__ aggu)
{
    int t = blockIdx.x * blockDim.x + threadIdx.x;
    int d = t >> 5, lane = t & 31;
    if (d >= NTOT) return;

    const int *start, *cnt, *perm, *srcidx;
    const float* feat;
    float* agg;
    if (d < NTXN) {
        start = startt; cnt = cntt; perm = permt; feat = featu; srcidx = ixu; agg = aggt;
    } else {
        d -= NTXN;
        start = startu; cnt = cntu; perm = permu; feat = featt; srcidx = ixt; agg = aggu;
    }

    int s = __ldg(start + d), c = __ldg(cnt + d);
    float4 acc = make_float4(0.f, 0.f, 0.f, 0.f);
    for (int j = 0; j < c; j++) {
        int src = __ldg(perm + s + j);
        if (srcidx) src = __ldg(srcidx + src);
        float4 v = __ldg((const float4*)(feat + (size_t)src * HDIM) + lane);
        acc.x += v.x; acc.y += v.y; acc.z += v.z; acc.w += v.w;
    }
    float sc = 1.f / (float)(c > 1 ? c : 1);
    acc.x *= sc; acc.y *= sc; acc.z *= sc; acc.w *= sc;
    ((float4*)(agg + (size_t)d * HDIM))[lane] = acc;
}

// ===================== weight prep =====================
__global__ void wprep(const float* __restrict__ Wl, const float* __restrict__ Wr) {
    int lt = blockIdx.x;
    const float* wl = Wl + (size_t)lt * HDIM * HDIM;
    const float* wr = Wr + (size_t)lt * HDIM * HDIM;
    unsigned char* dhi = (unsigned char*)g_wimg + (size_t)lt * 131072;
    unsigned char* dlo = dhi + 65536;
    for (int e = threadIdx.x; e < 256 * 128; e += blockDim.x) {
        int k = e >> 7, n = e & 127;
        float v = (k < 128) ? __ldg(wl + k * HDIM + n) : __ldg(wr + (k - 128) * HDIM + n);
        __nv_bfloat16 hi = __float2bfloat16_rn(v);
        __nv_bfloat16 lo = __float2bfloat16_rn(v - __bfloat162float(hi));
        uint32_t off = (uint32_t)n * 512 + (((uint32_t)k * 2) ^ (uint32_t)((n & 7) * 16));
        *(__nv_bfloat16*)(dhi + off) = hi;
        *(__nv_bfloat16*)(dlo + off) = lo;
    }
}
__global__ void w1prep(const float* __restrict__ W1) {
    unsigned char* dhi = (unsigned char*)g_w1img;
    unsigned char* dlo = dhi + 16384;
    for (int e = blockIdx.x * blockDim.x + threadIdx.x; e < 128 * 64; e += gridDim.x * blockDim.x) {
        int k = e >> 6, n = e & 63;
        float v = __ldg(W1 + k * HID2 + n);
        __nv_bfloat16 hi = __float2bfloat16_rn(v);
        __nv_bfloat16 lo = __float2bfloat16_rn(v - __bfloat162float(hi));
        uint32_t off = (uint32_t)n * 256 + (((uint32_t)k * 2) ^ (uint32_t)((n & 7) * 16));
        *(__nv_bfloat16*)(dhi + off) = hi;
        *(__nv_bfloat16*)(dlo + off) = lo;
    }
}

// ===================== merged persistent dual GEMM (both node types, one launch) ==========
// Segment 0: txn tiles (Mt rows), segment 1: user tiles (Mu rows). Weights/BN re-staged
// once per CTA at the segment switch.
#define SMB_SCL 0
#define SMB_SFT 512
#define SMB_BHI 1024
#define SMB_BLO (1024 + 65536)
#define SMB_TOT (1024 + 131072)

__global__ __launch_bounds__(256, 1) void gemm_both(
    const float* __restrict__ A1t, const float* __restrict__ selft, const int* __restrict__ ixt,
    const float4* __restrict__ wimgt, const float* __restrict__ biast,
    const float* __restrict__ gmat, const float* __restrict__ btat,
    const float* __restrict__ mut,  const float* __restrict__ vart,
    float* __restrict__ outt, int Mt,
    const float* __restrict__ A1u, const float* __restrict__ selfu, const int* __restrict__ ixu,
    const float4* __restrict__ wimgu, const float* __restrict__ biasu,
    const float* __restrict__ gmau, const float* __restrict__ btau,
    const float* __restrict__ muu,  const float* __restrict__ varu,
    float* __restrict__ outu, int Mu)
{
    extern __shared__ char smem[];
    uint32_t sb = smem_to_u32(smem);
    const int tid  = threadIdx.x;
    const int lane = tid & 31;
    const int wid  = tid >> 5;

    const int warp_m = wid & 3;
    const int warp_n = wid >> 2;
    const int n0 = warp_n * 64;
    const int g  = lane >> 2;
    const int tg = lane & 3;

    const int n_off  = (lane & 7) + ((lane >> 4) << 3);
    const int k_half = (lane & 8) << 1;
    const uint32_t xorv = (uint32_t)((n_off & 7) << 4);
    uint32_t brow_hi[4], brow_lo[4];
    #pragma unroll
    for (int np = 0; np < 4; np++) {
        uint32_t nrow = (uint32_t)(n0 + np * 16 + n_off) * 512u;
        brow_hi[np] = sb + SMB_BHI + nrow;
        brow_lo[np] = sb + SMB_BLO + nrow;
    }
    const float* scl = (const float*)(smem + SMB_SCL);
    const float* sft = (const float*)(smem + SMB_SFT);

    const int ntt = (Mt + 127) >> 7;
    const int ntu = (Mu + 127) >> 7;
    const int ntiles = ntt + ntu;

    int cur_seg = -1;
    for (int tile = blockIdx.x; tile < ntiles; tile += gridDim.x) {
        const int seg = (tile >= ntt) ? 1 : 0;

        // segment-local views
        const float* A1     = seg ? A1u   : A1t;
        const float* self   = seg ? selfu : selft;
        const int*   selfix = seg ? ixu   : ixt;
        float*       out    = seg ? outu  : outt;
        const int    M      = seg ? Mu    : Mt;
        const int    ltile  = seg ? (tile - ntt) : tile;

        if (seg != cur_seg) {
            __syncthreads();   // prior tile's smem reads complete
            const float4* wimg = seg ? wimgu : wimgt;
            float4* bs = (float4*)(smem + SMB_BHI);
            #pragma unroll 4
            for (int i = tid; i < 8192; i += 256) bs[i] = __ldg(wimg + i);
            if (tid < HDIM) {
                const float* var = seg ? varu : vart;
                const float* gma = seg ? gmau : gmat;
                const float* bta = seg ? btau : btat;
                const float* bia = seg ? biasu : biast;
                const float* mu_ = seg ? muu : mut;
                float rs = rsqrtf(__ldg(var + tid) + EPSV) * __ldg(gma + tid);
                ((float*)(smem + SMB_SCL))[tid] = rs;
                ((float*)(smem + SMB_SFT))[tid] = __ldg(bta + tid) + (__ldg(bia + tid) - __ldg(mu_ + tid)) * rs;
            }
            __syncthreads();
            cur_seg = seg;
        }

        const int m0 = ltile * 128 + warp_m * 32;

        const float* pa1[4];
        const float* pa2[4];
        #pragma unroll
        for (int i = 0; i < 4; i++) {
            int r = m0 + g + i * 8;
            r = r < M ? r : (M - 1);
            pa1[i] = A1 + (size_t)r * HDIM;
            int sr = selfix ? __ldg(selfix + r) : r;
            pa2[i] = self + (size_t)sr * HDIM;
        }

        float acc[2][8][4];
        #pragma unroll
        for (int mt = 0; mt < 2; mt++)
            #pragma unroll
            for (int nt = 0; nt < 8; nt++)
                #pragma unroll
                for (int q = 0; q < 4; q++) acc[mt][nt][q] = 0.f;

        // ---- software-pipelined k-loop ----
        float2 xc[4][2];
        {
            int k0 = tg * 2;
            #pragma unroll
            for (int i = 0; i < 4; i++) {
                xc[i][0] = *(const float2*)(pa1[i] + k0);
                xc[i][1] = *(const float2*)(pa1[i] + k0 + 8);
            }
        }
        #pragma unroll 2
        for (int kk = 0; kk < 16; kk++) {
            uint32_t ah[2][4], al[2][4];
            #pragma unroll
            for (int mt = 0; mt < 2; mt++) {
                int i0 = mt * 2, i1 = mt * 2 + 1;
                split2(xc[i0][0].x, xc[i0][0].y, ah[mt][0], al[mt][0]);
                split2(xc[i1][0].x, xc[i1][0].y, ah[mt][1], al[mt][1]);
                split2(xc[i0][1].x, xc[i0][1].y, ah[mt][2], al[mt][2]);
                split2(xc[i1][1].x, xc[i1][1].y, ah[mt][3], al[mt][3]);
            }
            float2 xn[4][2];
            if (kk < 15) {
                int kn = kk + 1;
                int k0 = (kn & 7) * 16 + tg * 2;
                if (kn < 8) {
                    #pragma unroll
                    for (int i = 0; i < 4; i++) {
                        xn[i][0] = *(const float2*)(pa1[i] + k0);
                        xn[i][1] = *(const float2*)(pa1[i] + k0 + 8);
                    }
                } else {
                    #pragma unroll
                    for (int i = 0; i < 4; i++) {
                        xn[i][0] = *(const float2*)(pa2[i] + k0);
                        xn[i][1] = *(const float2*)(pa2[i] + k0 + 8);
                    }
                }
            }
            uint32_t kterm = (uint32_t)((kk * 32 + k_half)) ^ xorv;
            #pragma unroll
            for (int np = 0; np < 4; np++) {
                uint32_t bh0, bh1, bh2, bh3, bl0, bl1, bl2, bl3;
                LDSM_X4(bh0, bh1, bh2, bh3, brow_hi[np] + kterm);
                LDSM_X4(bl0, bl1, bl2, bl3, brow_lo[np] + kterm);
                #pragma unroll
                for (int mt = 0; mt < 2; mt++) {
                    MMA_BF16(acc[mt][2 * np],     ah[mt], bh0, bh1);
                    MMA_BF16(acc[mt][2 * np],     al[mt], bh0, bh1);
                    MMA_BF16(acc[mt][2 * np],     ah[mt], bl0, bl1);
                    MMA_BF16(acc[mt][2 * np + 1], ah[mt], bh2, bh3);
                    MMA_BF16(acc[mt][2 * np + 1], al[mt], bh2, bh3);
                    MMA_BF16(acc[mt][2 * np + 1], ah[mt], bl2, bl3);
                }
            }
            if (kk < 15) {
                #pragma unroll
                for (int i = 0; i < 4; i++) { xc[i][0] = xn[i][0]; xc[i][1] = xn[i][1]; }
            }
        }

        // ---- epilogue (out distinct from inputs) ----
        #pragma unroll
        for (int mt = 0; mt < 2; mt++) {
            int r_lo = m0 + mt * 16 + g;
            int r_hi = r_lo + 8;
            #pragma unroll
            for (int nt = 0; nt < 8; nt++) {
                int c = n0 + nt * 8 + tg * 2;
                float s0 = scl[c], s1 = scl[c + 1];
                float f0 = sft[c], f1 = sft[c + 1];
                if (r_lo < M) {
                    float2 o;
                    o.x = fmaxf(fmaf(acc[mt][nt][0], s0, f0), 0.f);
                    o.y = fmaxf(fmaf(acc[mt][nt][1], s1, f1), 0.f);
                    *(float2*)(out + (size_t)r_lo * HDIM + c) = o;
                }
                if (r_hi < M) {
                    float2 o;
                    o.x = fmaxf(fmaf(acc[mt][nt][2], s0, f0), 0.f);
                    o.y = fmaxf(fmaf(acc[mt][nt][3], s1, f1), 0.f);
                    *(float2*)(out + (size_t)r_hi * HDIM + c) = o;
                }
            }
        }
    }
}

// ===================== tensor-core MLP head =====================
__global__ __launch_bounds__(256, 2) void mlp_mma(
    const float* __restrict__ hu, const float* __restrict__ ht,
    const float4* __restrict__ w1img,
    const float* __restrict__ b1, const float* __restrict__ W2, const float* __restrict__ b2,
    float* __restrict__ out)
{
    __shared__ float4 sB[2048];
    __shared__ float sb1[HID2];
    __shared__ float sW2[HID2 * OUTD];
    __shared__ float sb2[OUTD];
    for (int i = threadIdx.x; i < 2048; i += 256) sB[i] = __ldg(w1img + i);
    if (threadIdx.x < HID2) sb1[threadIdx.x] = __ldg(b1 + threadIdx.x);
    if (threadIdx.x < HID2 * OUTD) sW2[threadIdx.x] = __ldg(W2 + threadIdx.x);
    if (threadIdx.x < OUTD) sb2[threadIdx.x] = __ldg(b2 + threadIdx.x);
    __syncthreads();

    const int lane = threadIdx.x & 31;
    const int wid  = threadIdx.x >> 5;
    const int m0 = blockIdx.x * 256 + wid * 32;
    const int g  = lane >> 2;
    const int tg = lane & 3;

    const float* pa[4];
    #pragma unroll
    for (int i = 0; i < 4; i++) {
        int r = m0 + g + i * 8;
        r = r < NTOT ? r : (NTOT - 1);
        pa[i] = (r < NUSR) ? hu + (size_t)r * HDIM : ht + (size_t)(r - NUSR) * HDIM;
    }

    const int n_off  = (lane & 7) + ((lane >> 4) << 3);
    const int k_half = (lane & 8) << 1;
    const uint32_t xorv = (uint32_t)((n_off & 7) << 4);
    uint32_t sbu = smem_to_u32(sB);
    uint32_t brow_hi[4], brow_lo[4];
    #pragma unroll
    for (int np = 0; np < 4; np++) {
        uint32_t nrow = (uint32_t)(np * 16 + n_off) * 256u;
        brow_hi[np] = sbu + nrow;
        brow_lo[np] = sbu + 16384u + nrow;
    }

    float acc[2][8][4];
    #pragma unroll
    for (int mt = 0; mt < 2; mt++)
        #pragma unroll
        for (int nt = 0; nt < 8; nt++)
            #pragma unroll
            for (int q = 0; q < 4; q++) acc[mt][nt][q] = 0.f;

    #pragma unroll 2
    for (int kk = 0; kk < 8; kk++) {
        int k0 = kk * 16 + tg * 2;
        float2 x[4][2];
        #pragma unroll
        for (int i = 0; i < 4; i++) {
            x[i][0] = *(const float2*)(pa[i] + k0);
            x[i][1] = *(const float2*)(pa[i] + k0 + 8);
        }
        uint32_t ah[2][4], al[2][4];
        #pragma unroll
        for (int mt = 0; mt < 2; mt++) {
            int i0 = mt * 2, i1 = mt * 2 + 1;
            split2(x[i0][0].x, x[i0][0].y, ah[mt][0], al[mt][0]);
            split2(x[i1][0].x, x[i1][0].y, ah[mt][1], al[mt][1]);
            split2(x[i0][1].x, x[i0][1].y, ah[mt][2], al[mt][2]);
            split2(x[i1][1].x, x[i1][1].y, ah[mt][3], al[mt][3]);
        }
        uint32_t kterm = (uint32_t)((kk * 32 + k_half)) ^ xorv;
        #pragma unroll
        for (int np = 0; np < 4; np++) {
            uint32_t bh0, bh1, bh2, bh3, bl0, bl1, bl2, bl3;
            LDSM_X4(bh0, bh1, bh2, bh3, brow_hi[np] + kterm);
            LDSM_X4(bl0, bl1, bl2, bl3, brow_lo[np] + kterm);
            #pragma unroll
            for (int mt = 0; mt < 2; mt++) {
                MMA_BF16(acc[mt][2 * np],     ah[mt], bh0, bh1);
                MMA_BF16(acc[mt][2 * np],     al[mt], bh0, bh1);
                MMA_BF16(acc[mt][2 * np],     ah[mt], bl0, bl1);
                MMA_BF16(acc[mt][2 * np + 1], ah[mt], bh2, bh3);
                MMA_BF16(acc[mt][2 * np + 1], al[mt], bh2, bh3);
                MMA_BF16(acc[mt][2 * np + 1], ah[mt], bl2, bl3);
            }
        }
    }

    #pragma unroll
    for (int mt = 0; mt < 2; mt++) {
        #pragma unroll
        for (int half = 0; half < 2; half++) {
            int row = m0 + mt * 16 + g + half * 8;
            float oA = 0.f, oB = 0.f;
            #pragma unroll
            for (int nt = 0; nt < 8; nt++) {
                int c = nt * 8 + tg * 2;
                float h0 = fmaxf(acc[mt][nt][half * 2 + 0] + sb1[c],     0.f);
                float h1 = fmaxf(acc[mt][nt][half * 2 + 1] + sb1[c + 1], 0.f);
                oA = fmaf(h0, sW2[c * OUTD],     fmaf(h1, sW2[(c + 1) * OUTD],     oA));
                oB = fmaf(h0, sW2[c * OUTD + 1], fmaf(h1, sW2[(c + 1) * OUTD + 1], oB));
            }
            oA += __shfl_xor_sync(0xffffffffu, oA, 1);
            oA += __shfl_xor_sync(0xffffffffu, oA, 2);
            oB += __shfl_xor_sync(0xffffffffu, oB, 1);
            oB += __shfl_xor_sync(0xffffffffu, oB, 2);
            if (tg == 0 && row < NTOT) {
                out[(size_t)row * OUTD + 0] = oA + sb2[0];
                out[(size_t)row * OUTD + 1] = oB + sb2[1];
            }
        }
    }
}

// ===================== launcher =====================
extern "C" void kernel_launch(void* const* d_in, const int* in_sizes, int n_in,
                              void* d_out, int out_size) {
    (void)in_sizes; (void)n_in; (void)out_size;
    const int*   x_user  = (const int*)  d_in[0];
    const int*   x_txn   = (const int*)  d_in[1];
    const int*   ei0_src = (const int*)  d_in[2];
    const int*   ei0_dst = (const int*)  d_in[3];
    const int*   ei1_src = (const int*)  d_in[4];
    const int*   ei1_dst = (const int*)  d_in[5];
    const float* emb_u   = (const float*)d_in[6];
    const float* emb_t   = (const float*)d_in[7];
    const float* Wl      = (const float*)d_in[8];
    const float* bl      = (const float*)d_in[9];
    const float* Wr      = (const float*)d_in[10];
    const float* bn_g    = (const float*)d_in[11];
    const float* bn_b    = (const float*)d_in[12];
    const float* bn_m    = (const float*)d_in[13];
    const float* bn_v    = (const float*)d_in[14];
    const float* W1      = (const float*)d_in[15];
    const float* b1      = (const float*)d_in[16];
    const float* W2      = (const float*)d_in[17];
    const float* b2      = (const float*)d_in[18];
    float* out = (float*)d_out;

    float *hu[2], *ht[2], *aggu, *aggt;
    int *cntu, *cntt, *startu, *startt, *tmpu, *tmpt, *permu, *permt, *cursor;
    float4 *wimg, *w1img;
    cudaGetSymbolAddress((void**)&hu[0],  g_hu0);
    cudaGetSymbolAddress((void**)&hu[1],  g_hu1);
    cudaGetSymbolAddress((void**)&ht[0],  g_ht0);
    cudaGetSymbolAddress((void**)&ht[1],  g_ht1);
    cudaGetSymbolAddress((void**)&aggu,   g_aggu);
    cudaGetSymbolAddress((void**)&aggt,   g_aggt);
    cudaGetSymbolAddress((void**)&cntu,   g_cntu);
    cudaGetSymbolAddress((void**)&cntt,   g_cntt);
    cudaGetSymbolAddress((void**)&startu, g_startu);
    cudaGetSymbolAddress((void**)&startt, g_startt);
    cudaGetSymbolAddress((void**)&tmpu,   g_tmpu);
    cudaGetSymbolAddress((void**)&tmpt,   g_tmpt);
    cudaGetSymbolAddress((void**)&permu,  g_permu);
    cudaGetSymbolAddress((void**)&permt,  g_permt);
    cudaGetSymbolAddress((void**)&cursor, g_cursor);
    cudaGetSymbolAddress((void**)&wimg,   g_wimg);
    cudaGetSymbolAddress((void**)&w1img,  g_w1img);

    cudaFuncSetAttribute(gemm_both, cudaFuncAttributeMaxDynamicSharedMemorySize, SMB_TOT);

    // 0) bake weight images
    wprep<<<6, 256>>>(Wl, Wr);
    w1prep<<<8, 256>>>(W1);

    // 1) CSR build (layer-invariant)
    zero_i<<<(NTXN + 255) / 256, 256>>>(cntt, NTXN);
    zero_i<<<(NUSR + 255) / 256, 256>>>(cntu, NUSR);
    zero_i<<<1, 32>>>(cursor, 2);
    count_deg<<<(NEDG + 255) / 256, 256>>>(ei0_dst, cntt, NEDG);
    count_deg<<<(NEDG + 255) / 256, 256>>>(ei1_dst, cntu, NEDG);
    assign_off<<<(NTXN + 255) / 256, 256>>>(cntt, startt, tmpt, cursor + 0, NTXN);
    assign_off<<<(NUSR + 255) / 256, 256>>>(cntu, startu, tmpu, cursor + 1, NUSR);
    fill_perm<<<(NEDG + 255) / 256, 256>>>(ei0_src, ei0_dst, tmpt, permt, NEDG);
    fill_perm<<<(NEDG + 255) / 256, 256>>>(ei1_src, ei1_dst, tmpu, permu, NEDG);

    // 2) layers: 2 launches each (merged agg + merged gemm)
    for (int l = 0; l < NLAY; l++) {
        const float* su  = (l == 0) ? emb_u : hu[(l + 1) & 1];
        const float* st_ = (l == 0) ? emb_t : ht[(l + 1) & 1];
        const int* ixu = (l == 0) ? x_user : nullptr;
        const int* ixt = (l == 0) ? x_txn  : nullptr;
        float* out_t = ht[l & 1];
        float* out_u = hu[l & 1];

        agg_both<<<((size_t)NTOT * 32 + 255) / 256, 256>>>(
            startt, cntt, permt, su,  ixu, aggt,
            startu, cntu, permu, st_, ixt, aggu);

        int lt0 = l * 2 + 0;   // txn weights/bias; BN (l,1)
        int lt1 = l * 2 + 1;   // user weights/bias; BN (l,0)
        gemm_both<<<NSM, 256, SMB_TOT>>>(
            aggt, st_, ixt,
            wimg + (size_t)lt0 * 8192, bl + (size_t)lt0 * HDIM,
            bn_g + (size_t)(l * 2 + 1) * HDIM, bn_b + (size_t)(l * 2 + 1) * HDIM,
            bn_m + (size_t)(l * 2 + 1) * HDIM, bn_v + (size_t)(l * 2 + 1) * HDIM,
            out_t, NTXN,
            aggu, su, ixu,
            wimg + (size_t)lt1 * 8192, bl + (size_t)lt1 * HDIM,
            bn_g + (size_t)(l * 2 + 0) * HDIM, bn_b + (size_t)(l * 2 + 0) * HDIM,
            bn_m + (size_t)(l * 2 + 0) * HDIM, bn_v + (size_t)(l * 2 + 0) * HDIM,
            out_u, NUSR);
    }

    // 3) MLP head (final layer wrote buffer index (NLAY-1)&1 = 0)
    mlp_mma<<<(NTOT + 255) / 256, 256>>>(hu[(NLAY - 1) & 1], ht[(NLAY - 1) & 1],
                                         w1img, b1, W2, b2, out);
}

// round 17
// speedup vs baseline: 1.2938x; 1.2027x over previous
#include <cuda_runtime.h>
#include <cuda_bf16.h>
#include <cstdint>

#define NUSR 100000
#define NTXN 400000
#define NEDG 400000
#define HDIM 128
#define NLAY 3
#define HID2 64
#define OUTD 2
#define EPSV 1e-5f
#define NTOT (NUSR + NTXN)
#define NSM  148
#define GTHR 384            // gemm CTA threads (12 warps)
#define GTIL 192            // gemm rows per CTA tile

// ===================== helpers =====================
__device__ __forceinline__ uint32_t smem_to_u32(const void* p) {
    uint32_t a;
    asm("{ .reg .u64 t; cvta.to.shared.u64 t, %1; cvt.u32.u64 %0, t; }" : "=r"(a) : "l"(p));
    return a;
}
__device__ __forceinline__ void split2(float x, float y, uint32_t& hi, uint32_t& lo) {
    __nv_bfloat162 h = __floats2bfloat162_rn(x, y);
    float rx = x - __bfloat162float(h.x);
    float ry = y - __bfloat162float(h.y);
    __nv_bfloat162 l = __floats2bfloat162_rn(rx, ry);
    hi = *(uint32_t*)&h;
    lo = *(uint32_t*)&l;
}
#define LDSM_X4(r0, r1, r2, r3, addr) \
    asm volatile("ldmatrix.sync.aligned.m8n8.x4.shared.b16 {%0,%1,%2,%3}, [%4];" \
                 : "=r"(r0), "=r"(r1), "=r"(r2), "=r"(r3) : "r"(addr))
#define MMA_BF16(d, a, b0, b1) \
    asm volatile("mma.sync.aligned.m16n8k16.row.col.f32.bf16.bf16.f32 " \
                 "{%0,%1,%2,%3}, {%4,%5,%6,%7}, {%8,%9}, {%0,%1,%2,%3};" \
                 : "+f"((d)[0]), "+f"((d)[1]), "+f"((d)[2]), "+f"((d)[3]) \
                 : "r"((a)[0]), "r"((a)[1]), "r"((a)[2]), "r"((a)[3]), "r"(b0), "r"(b1))

// ===================== scratch (device globals) =====================
__device__ float g_hu0[(size_t)NUSR * HDIM];
__device__ float g_hu1[(size_t)NUSR * HDIM];
__device__ float g_ht0[(size_t)NTXN * HDIM];
__device__ float g_ht1[(size_t)NTXN * HDIM];
__device__ float g_aggu[(size_t)NUSR * HDIM];
__device__ float g_aggt[(size_t)NTXN * HDIM];
__device__ int   g_cntu[NUSR];
__device__ int   g_cntt[NTXN];
__device__ int   g_startu[NUSR];
__device__ int   g_startt[NTXN];
__device__ int   g_tmpu[NUSR];
__device__ int   g_tmpt[NTXN];
__device__ int   g_permu[NEDG];
__device__ int   g_permt[NEDG];
__device__ int   g_cursor[2];
__device__ float4 g_wimg[6 * 2 * 4096];   // [6 (l,t)] x (hi 64KB + lo 64KB)
__device__ float4 g_w1img[2048];          // W1 hi 16KB + lo 16KB

// ===================== CSR build kernels =====================
__global__ void zero_i(int* __restrict__ p, int n) {
    int i = blockIdx.x * blockDim.x + threadIdx.x;
    if (i < n) p[i] = 0;
}
__global__ void count_deg(const int* __restrict__ dst, int* __restrict__ cnt, int n) {
    int i = blockIdx.x * blockDim.x + threadIdx.x;
    if (i < n) atomicAdd(&cnt[__ldg(dst + i)], 1);
}
__global__ void assign_off(const int* __restrict__ cnt, int* __restrict__ start,
                           int* __restrict__ tmp, int* cursor, int n) {
    __shared__ int wsum[8];
    __shared__ int sbase;
    int i = blockIdx.x * 256 + threadIdx.x;
    int lane = threadIdx.x & 31, w = threadIdx.x >> 5;
    int c = (i < n) ? __ldg(cnt + i) : 0;
    int pre = c;
    #pragma unroll
    for (int o = 1; o < 32; o <<= 1) {
        int u = __shfl_up_sync(0xffffffffu, pre, o);
        if (lane >= o) pre += u;
    }
    if (lane == 31) wsum[w] = pre;
    __syncthreads();
    if (threadIdx.x == 0) {
        int s = 0;
        #pragma unroll
        for (int j = 0; j < 8; j++) { int t = wsum[j]; wsum[j] = s; s += t; }
        sbase = atomicAdd(cursor, s);
    }
    __syncthreads();
    int off = sbase + wsum[w] + pre - c;
    if (i < n) { start[i] = off; tmp[i] = off; }
}
__global__ void fill_perm(const int* __restrict__ src, const int* __restrict__ dst,
                          int* __restrict__ tmp, int* __restrict__ perm, int n) {
    int i = blockIdx.x * blockDim.x + threadIdx.x;
    if (i < n) {
        int d = __ldg(dst + i);
        int slot = atomicAdd(&tmp[d], 1);
        perm[slot] = __ldg(src + i);
    }
}

// ===================== merged aggregation (both node types in one launch) =====================
__global__ void agg_both(
    const int* __restrict__ startt, const int* __restrict__ cntt, const int* __restrict__ permt,
    const float* __restrict__ featu, const int* __restrict__ ixu,
    float* __restrict__ aggt,
    const int* __restrict__ startu, const int* __restrict__ cntu, const int* __restrict__ permu,
    const float* __restrict__ featt, const int* __restrict__ ixt,
    float* __restrict__ aggu)
{
    int t = blockIdx.x * blockDim.x + threadIdx.x;
    int d = t >> 5, lane = t & 31;
    if (d >= NTOT) return;

    const int *start, *cnt, *perm, *srcidx;
    const float* feat;
    float* agg;
    if (d < NTXN) {
        start = startt; cnt = cntt; perm = permt; feat = featu; srcidx = ixu; agg = aggt;
    } else {
        d -= NTXN;
        start = startu; cnt = cntu; perm = permu; feat = featt; srcidx = ixt; agg = aggu;
    }

    int s = __ldg(start + d), c = __ldg(cnt + d);
    float4 acc = make_float4(0.f, 0.f, 0.f, 0.f);
    for (int j = 0; j < c; j++) {
        int src = __ldg(perm + s + j);
        if (srcidx) src = __ldg(srcidx + src);
        float4 v = __ldg((const float4*)(feat + (size_t)src * HDIM) + lane);
        acc.x += v.x; acc.y += v.y; acc.z += v.z; acc.w += v.w;
    }
    float sc = 1.f / (float)(c > 1 ? c : 1);
    acc.x *= sc; acc.y *= sc; acc.z *= sc; acc.w *= sc;
    ((float4*)(agg + (size_t)d * HDIM))[lane] = acc;
}

// ===================== weight prep =====================
__global__ void wprep(const float* __restrict__ Wl, const float* __restrict__ Wr) {
    int lt = blockIdx.x;
    const float* wl = Wl + (size_t)lt * HDIM * HDIM;
    const float* wr = Wr + (size_t)lt * HDIM * HDIM;
    unsigned char* dhi = (unsigned char*)g_wimg + (size_t)lt * 131072;
    unsigned char* dlo = dhi + 65536;
    for (int e = threadIdx.x; e < 256 * 128; e += blockDim.x) {
        int k = e >> 7, n = e & 127;
        float v = (k < 128) ? __ldg(wl + k * HDIM + n) : __ldg(wr + (k - 128) * HDIM + n);
        __nv_bfloat16 hi = __float2bfloat16_rn(v);
        __nv_bfloat16 lo = __float2bfloat16_rn(v - __bfloat162float(hi));
        uint32_t off = (uint32_t)n * 512 + (((uint32_t)k * 2) ^ (uint32_t)((n & 7) * 16));
        *(__nv_bfloat16*)(dhi + off) = hi;
        *(__nv_bfloat16*)(dlo + off) = lo;
    }
}
__global__ void w1prep(const float* __restrict__ W1) {
    unsigned char* dhi = (unsigned char*)g_w1img;
    unsigned char* dlo = dhi + 16384;
    for (int e = blockIdx.x * blockDim.x + threadIdx.x; e < 128 * 64; e += gridDim.x * blockDim.x) {
        int k = e >> 6, n = e & 63;
        float v = __ldg(W1 + k * HID2 + n);
        __nv_bfloat16 hi = __float2bfloat16_rn(v);
        __nv_bfloat16 lo = __float2bfloat16_rn(v - __bfloat162float(hi));
        uint32_t off = (uint32_t)n * 256 + (((uint32_t)k * 2) ^ (uint32_t)((n & 7) * 16));
        *(__nv_bfloat16*)(dhi + off) = hi;
        *(__nv_bfloat16*)(dlo + off) = lo;
    }
}

// ===================== merged persistent dual GEMM (12 warps, 192-row tiles) ==========
#define SMB_SCL 0
#define SMB_SFT 512
#define SMB_BHI 1024
#define SMB_BLO (1024 + 65536)
#define SMB_TOT (1024 + 131072)

__global__ __launch_bounds__(GTHR, 1) void gemm_both(
    const float* __restrict__ A1t, const float* __restrict__ selft, const int* __restrict__ ixt,
    const float4* __restrict__ wimgt, const float* __restrict__ biast,
    const float* __restrict__ gmat, const float* __restrict__ btat,
    const float* __restrict__ mut,  const float* __restrict__ vart,
    float* __restrict__ outt, int Mt,
    const float* __restrict__ A1u, const float* __restrict__ selfu, const int* __restrict__ ixu,
    const float4* __restrict__ wimgu, const float* __restrict__ biasu,
    const float* __restrict__ gmau, const float* __restrict__ btau,
    const float* __restrict__ muu,  const float* __restrict__ varu,
    float* __restrict__ outu, int Mu)
{
    extern __shared__ char smem[];
    uint32_t sb = smem_to_u32(smem);
    const int tid  = threadIdx.x;
    const int lane = tid & 31;
    const int wid  = tid >> 5;

    const int warp_m = wid % 6;          // 6 m-blocks of 32 rows = 192
    const int warp_n = wid / 6;          // 2 n-blocks of 64 cols
    const int n0 = warp_n * 64;
    const int g  = lane >> 2;
    const int tg = lane & 3;

    const int n_off  = (lane & 7) + ((lane >> 4) << 3);
    const int k_half = (lane & 8) << 1;
    const uint32_t xorv = (uint32_t)((n_off & 7) << 4);
    uint32_t brow_hi[4], brow_lo[4];
    #pragma unroll
    for (int np = 0; np < 4; np++) {
        uint32_t nrow = (uint32_t)(n0 + np * 16 + n_off) * 512u;
        brow_hi[np] = sb + SMB_BHI + nrow;
        brow_lo[np] = sb + SMB_BLO + nrow;
    }
    const float* scl = (const float*)(smem + SMB_SCL);
    const float* sft = (const float*)(smem + SMB_SFT);

    const int ntt = (Mt + GTIL - 1) / GTIL;
    const int ntu = (Mu + GTIL - 1) / GTIL;
    const int ntiles = ntt + ntu;

    int cur_seg = -1;
    for (int tile = blockIdx.x; tile < ntiles; tile += gridDim.x) {
        const int seg = (tile >= ntt) ? 1 : 0;

        const float* A1     = seg ? A1u   : A1t;
        const float* self   = seg ? selfu : selft;
        const int*   selfix = seg ? ixu   : ixt;
        float*       out    = seg ? outu  : outt;
        const int    M      = seg ? Mu    : Mt;
        const int    ltile  = seg ? (tile - ntt) : tile;

        if (seg != cur_seg) {
            __syncthreads();
            const float4* wimg = seg ? wimgu : wimgt;
            float4* bs = (float4*)(smem + SMB_BHI);
            #pragma unroll 4
            for (int i = tid; i < 8192; i += GTHR) bs[i] = __ldg(wimg + i);
            if (tid < HDIM) {
                const float* var = seg ? varu : vart;
                const float* gma = seg ? gmau : gmat;
                const float* bta = seg ? btau : btat;
                const float* bia = seg ? biasu : biast;
                const float* mu_ = seg ? muu : mut;
                float rs = rsqrtf(__ldg(var + tid) + EPSV) * __ldg(gma + tid);
                ((float*)(smem + SMB_SCL))[tid] = rs;
                ((float*)(smem + SMB_SFT))[tid] = __ldg(bta + tid) + (__ldg(bia + tid) - __ldg(mu_ + tid)) * rs;
            }
            __syncthreads();
            cur_seg = seg;
        }

        const int m0 = ltile * GTIL + warp_m * 32;

        const float* pa1[4];
        const float* pa2[4];
        #pragma unroll
        for (int i = 0; i < 4; i++) {
            int r = m0 + g + i * 8;
            r = r < M ? r : (M - 1);
            pa1[i] = A1 + (size_t)r * HDIM;
            int sr = selfix ? __ldg(selfix + r) : r;
            pa2[i] = self + (size_t)sr * HDIM;
        }

        float acc[2][8][4];
        #pragma unroll
        for (int mt = 0; mt < 2; mt++)
            #pragma unroll
            for (int nt = 0; nt < 8; nt++)
                #pragma unroll
                for (int q = 0; q < 4; q++) acc[mt][nt][q] = 0.f;

        // ---- software-pipelined k-loop ----
        float2 xc[4][2];
        {
            int k0 = tg * 2;
            #pragma unroll
            for (int i = 0; i < 4; i++) {
                xc[i][0] = *(const float2*)(pa1[i] + k0);
                xc[i][1] = *(const float2*)(pa1[i] + k0 + 8);
            }
        }
        #pragma unroll 2
        for (int kk = 0; kk < 16; kk++) {
            uint32_t ah[2][4], al[2][4];
            #pragma unroll
            for (int mt = 0; mt < 2; mt++) {
                int i0 = mt * 2, i1 = mt * 2 + 1;
                split2(xc[i0][0].x, xc[i0][0].y, ah[mt][0], al[mt][0]);
                split2(xc[i1][0].x, xc[i1][0].y, ah[mt][1], al[mt][1]);
                split2(xc[i0][1].x, xc[i0][1].y, ah[mt][2], al[mt][2]);
                split2(xc[i1][1].x, xc[i1][1].y, ah[mt][3], al[mt][3]);
            }
            float2 xn[4][2];
            if (kk < 15) {
                int kn = kk + 1;
                int k0 = (kn & 7) * 16 + tg * 2;
                if (kn < 8) {
                    #pragma unroll
                    for (int i = 0; i < 4; i++) {
                        xn[i][0] = *(const float2*)(pa1[i] + k0);
                        xn[i][1] = *(const float2*)(pa1[i] + k0 + 8);
                    }
                } else {
                    #pragma unroll
                    for (int i = 0; i < 4; i++) {
                        xn[i][0] = *(const float2*)(pa2[i] + k0);
                        xn[i][1] = *(const float2*)(pa2[i] + k0 + 8);
                    }
                }
            }
            uint32_t kterm = (uint32_t)((kk * 32 + k_half)) ^ xorv;
            #pragma unroll
            for (int np = 0; np < 4; np++) {
                uint32_t bh0, bh1, bh2, bh3, bl0, bl1, bl2, bl3;
                LDSM_X4(bh0, bh1, bh2, bh3, brow_hi[np] + kterm);
                LDSM_X4(bl0, bl1, bl2, bl3, brow_lo[np] + kterm);
                #pragma unroll
                for (int mt = 0; mt < 2; mt++) {
                    MMA_BF16(acc[mt][2 * np],     ah[mt], bh0, bh1);
                    MMA_BF16(acc[mt][2 * np],     al[mt], bh0, bh1);
                    MMA_BF16(acc[mt][2 * np],     ah[mt], bl0, bl1);
                    MMA_BF16(acc[mt][2 * np + 1], ah[mt], bh2, bh3);
                    MMA_BF16(acc[mt][2 * np + 1], al[mt], bh2, bh3);
                    MMA_BF16(acc[mt][2 * np + 1], ah[mt], bl2, bl3);
                }
            }
            if (kk < 15) {
                #pragma unroll
                for (int i = 0; i < 4; i++) { xc[i][0] = xn[i][0]; xc[i][1] = xn[i][1]; }
            }
        }

        // ---- epilogue ----
        #pragma unroll
        for (int mt = 0; mt < 2; mt++) {
            int r_lo = m0 + mt * 16 + g;
            int r_hi = r_lo + 8;
            #pragma unroll
            for (int nt = 0; nt < 8; nt++) {
                int c = n0 + nt * 8 + tg * 2;
                float s0 = scl[c], s1 = scl[c + 1];
                float f0 = sft[c], f1 = sft[c + 1];
                if (r_lo < M) {
                    float2 o;
                    o.x = fmaxf(fmaf(acc[mt][nt][0], s0, f0), 0.f);
                    o.y = fmaxf(fmaf(acc[mt][nt][1], s1, f1), 0.f);
                    *(float2*)(out + (size_t)r_lo * HDIM + c) = o;
                }
                if (r_hi < M) {
                    float2 o;
                    o.x = fmaxf(fmaf(acc[mt][nt][2], s0, f0), 0.f);
                    o.y = fmaxf(fmaf(acc[mt][nt][3], s1, f1), 0.f);
                    *(float2*)(out + (size_t)r_hi * HDIM + c) = o;
                }
            }
        }
    }
}

// ===================== tensor-core MLP head =====================
__global__ __launch_bounds__(256, 2) void mlp_mma(
    const float* __restrict__ hu, const float* __restrict__ ht,
    const float4* __restrict__ w1img,
    const float* __restrict__ b1, const float* __restrict__ W2, const float* __restrict__ b2,
    float* __restrict__ out)
{
    __shared__ float4 sB[2048];
    __shared__ float sb1[HID2];
    __shared__ float sW2[HID2 * OUTD];
    __shared__ float sb2[OUTD];
    for (int i = threadIdx.x; i < 2048; i += 256) sB[i] = __ldg(w1img + i);
    if (threadIdx.x < HID2) sb1[threadIdx.x] = __ldg(b1 + threadIdx.x);
    if (threadIdx.x < HID2 * OUTD) sW2[threadIdx.x] = __ldg(W2 + threadIdx.x);
    if (threadIdx.x < OUTD) sb2[threadIdx.x] = __ldg(b2 + threadIdx.x);
    __syncthreads();

    const int lane = threadIdx.x & 31;
    const int wid  = threadIdx.x >> 5;
    const int m0 = blockIdx.x * 256 + wid * 32;
    const int g  = lane >> 2;
    const int tg = lane & 3;

    const float* pa[4];
    #pragma unroll
    for (int i = 0; i < 4; i++) {
        int r = m0 + g + i * 8;
        r = r < NTOT ? r : (NTOT - 1);
        pa[i] = (r < NUSR) ? hu + (size_t)r * HDIM : ht + (size_t)(r - NUSR) * HDIM;
    }

    const int n_off  = (lane & 7) + ((lane >> 4) << 3);
    const int k_half = (lane & 8) << 1;
    const uint32_t xorv = (uint32_t)((n_off & 7) << 4);
    uint32_t sbu = smem_to_u32(sB);
    uint32_t brow_hi[4], brow_lo[4];
    #pragma unroll
    for (int np = 0; np < 4; np++) {
        uint32_t nrow = (uint32_t)(np * 16 + n_off) * 256u;
        brow_hi[np] = sbu + nrow;
        brow_lo[np] = sbu + 16384u + nrow;
    }

    float acc[2][8][4];
    #pragma unroll
    for (int mt = 0; mt < 2; mt++)
        #pragma unroll
        for (int nt = 0; nt < 8; nt++)
            #pragma unroll
            for (int q = 0; q < 4; q++) acc[mt][nt][q] = 0.f;

    #pragma unroll 2
    for (int kk = 0; kk < 8; kk++) {
        int k0 = kk * 16 + tg * 2;
        float2 x[4][2];
        #pragma unroll
        for (int i = 0; i < 4; i++) {
            x[i][0] = *(const float2*)(pa[i] + k0);
            x[i][1] = *(const float2*)(pa[i] + k0 + 8);
        }
        uint32_t ah[2][4], al[2][4];
        #pragma unroll
        for (int mt = 0; mt < 2; mt++) {
            int i0 = mt * 2, i1 = mt * 2 + 1;
            split2(x[i0][0].x, x[i0][0].y, ah[mt][0], al[mt][0]);
            split2(x[i1][0].x, x[i1][0].y, ah[mt][1], al[mt][1]);
            split2(x[i0][1].x, x[i0][1].y, ah[mt][2], al[mt][2]);
            split2(x[i1][1].x, x[i1][1].y, ah[mt][3], al[mt][3]);
        }
        uint32_t kterm = (uint32_t)((kk * 32 + k_half)) ^ xorv;
        #pragma unroll
        for (int np = 0; np < 4; np++) {
            uint32_t bh0, bh1, bh2, bh3, bl0, bl1, bl2, bl3;
            LDSM_X4(bh0, bh1, bh2, bh3, brow_hi[np] + kterm);
            LDSM_X4(bl0, bl1, bl2, bl3, brow_lo[np] + kterm);
            #pragma unroll
            for (int mt = 0; mt < 2; mt++) {
                MMA_BF16(acc[mt][2 * np],     ah[mt], bh0, bh1);
                MMA_BF16(acc[mt][2 * np],     al[mt], bh0, bh1);
                MMA_BF16(acc[mt][2 * np],     ah[mt], bl0, bl1);
                MMA_BF16(acc[mt][2 * np + 1], ah[mt], bh2, bh3);
                MMA_BF16(acc[mt][2 * np + 1], al[mt], bh2, bh3);
                MMA_BF16(acc[mt][2 * np + 1], ah[mt], bl2, bl3);
            }
        }
    }

    #pragma unroll
    for (int mt = 0; mt < 2; mt++) {
        #pragma unroll
        for (int half = 0; half < 2; half++) {
            int row = m0 + mt * 16 + g + half * 8;
            float oA = 0.f, oB = 0.f;
            #pragma unroll
            for (int nt = 0; nt < 8; nt++) {
                int c = nt * 8 + tg * 2;
                float h0 = fmaxf(acc[mt][nt][half * 2 + 0] + sb1[c],     0.f);
                float h1 = fmaxf(acc[mt][nt][half * 2 + 1] + sb1[c + 1], 0.f);
                oA = fmaf(h0, sW2[c * OUTD],     fmaf(h1, sW2[(c + 1) * OUTD],     oA));
                oB = fmaf(h0, sW2[c * OUTD + 1], fmaf(h1, sW2[(c + 1) * OUTD + 1], oB));
            }
            oA += __shfl_xor_sync(0xffffffffu, oA, 1);
            oA += __shfl_xor_sync(0xffffffffu, oA, 2);
            oB += __shfl_xor_sync(0xffffffffu, oB, 1);
            oB += __shfl_xor_sync(0xffffffffu, oB, 2);
            if (tg == 0 && row < NTOT) {
                out[(size_t)row * OUTD + 0] = oA + sb2[0];
                out[(size_t)row * OUTD + 1] = oB + sb2[1];
            }
        }
    }
}

// ===================== launcher =====================
extern "C" void kernel_launch(void* const* d_in, const int* in_sizes, int n_in,
                              void* d_out, int out_size) {
    (void)in_sizes; (void)n_in; (void)out_size;
    const int*   x_user  = (const int*)  d_in[0];
    const int*   x_txn   = (const int*)  d_in[1];
    const int*   ei0_src = (const int*)  d_in[2];
    const int*   ei0_dst = (const int*)  d_in[3];
    const int*   ei1_src = (const int*)  d_in[4];
    const int*   ei1_dst = (const int*)  d_in[5];
    const float* emb_u   = (const float*)d_in[6];
    const float* emb_t   = (const float*)d_in[7];
    const float* Wl      = (const float*)d_in[8];
    const float* bl      = (const float*)d_in[9];
    const float* Wr      = (const float*)d_in[10];
    const float* bn_g    = (const float*)d_in[11];
    const float* bn_b    = (const float*)d_in[12];
    const float* bn_m    = (const float*)d_in[13];
    const float* bn_v    = (const float*)d_in[14];
    const float* W1      = (const float*)d_in[15];
    const float* b1      = (const float*)d_in[16];
    const float* W2      = (const float*)d_in[17];
    const float* b2      = (const float*)d_in[18];
    float* out = (float*)d_out;

    float *hu[2], *ht[2], *aggu, *aggt;
    int *cntu, *cntt, *startu, *startt, *tmpu, *tmpt, *permu, *permt, *cursor;
    float4 *wimg, *w1img;
    cudaGetSymbolAddress((void**)&hu[0],  g_hu0);
    cudaGetSymbolAddress((void**)&hu[1],  g_hu1);
    cudaGetSymbolAddress((void**)&ht[0],  g_ht0);
    cudaGetSymbolAddress((void**)&ht[1],  g_ht1);
    cudaGetSymbolAddress((void**)&aggu,   g_aggu);
    cudaGetSymbolAddress((void**)&aggt,   g_aggt);
    cudaGetSymbolAddress((void**)&cntu,   g_cntu);
    cudaGetSymbolAddress((void**)&cntt,   g_cntt);
    cudaGetSymbolAddress((void**)&startu, g_startu);
    cudaGetSymbolAddress((void**)&startt, g_startt);
    cudaGetSymbolAddress((void**)&tmpu,   g_tmpu);
    cudaGetSymbolAddress((void**)&tmpt,   g_tmpt);
    cudaGetSymbolAddress((void**)&permu,  g_permu);
    cudaGetSymbolAddress((void**)&permt,  g_permt);
    cudaGetSymbolAddress((void**)&cursor, g_cursor);
    cudaGetSymbolAddress((void**)&wimg,   g_wimg);
    cudaGetSymbolAddress((void**)&w1img,  g_w1img);

    cudaFuncSetAttribute(gemm_both, cudaFuncAttributeMaxDynamicSharedMemorySize, SMB_TOT);

    // 0) bake weight images
    wprep<<<6, 256>>>(Wl, Wr);
    w1prep<<<8, 256>>>(W1);

    // 1) CSR build (layer-invariant)
    zero_i<<<(NTXN + 255) / 256, 256>>>(cntt, NTXN);
    zero_i<<<(NUSR + 255) / 256, 256>>>(cntu, NUSR);
    zero_i<<<1, 32>>>(cursor, 2);
    count_deg<<<(NEDG + 255) / 256, 256>>>(ei0_dst, cntt, NEDG);
    count_deg<<<(NEDG + 255) / 256, 256>>>(ei1_dst, cntu, NEDG);
    assign_off<<<(NTXN + 255) / 256, 256>>>(cntt, startt, tmpt, cursor + 0, NTXN);
    assign_off<<<(NUSR + 255) / 256, 256>>>(cntu, startu, tmpu, cursor + 1, NUSR);
    fill_perm<<<(NEDG + 255) / 256, 256>>>(ei0_src, ei0_dst, tmpt, permt, NEDG);
    fill_perm<<<(NEDG + 255) / 256, 256>>>(ei1_src, ei1_dst, tmpu, permu, NEDG);

    // 2) layers: 2 launches each
    for (int l = 0; l < NLAY; l++) {
        const float* su  = (l == 0) ? emb_u : hu[(l + 1) & 1];
        const float* st_ = (l == 0) ? emb_t : ht[(l + 1) & 1];
        const int* ixu = (l == 0) ? x_user : nullptr;
        const int* ixt = (l == 0) ? x_txn  : nullptr;
        float* out_t = ht[l & 1];
        float* out_u = hu[l & 1];

        agg_both<<<((size_t)NTOT * 32 + 255) / 256, 256>>>(
            startt, cntt, permt, su,  ixu, aggt,
            startu, cntu, permu, st_, ixt, aggu);

        int lt0 = l * 2 + 0;
        int lt1 = l * 2 + 1;
        gemm_both<<<NSM, GTHR, SMB_TOT>>>(
            aggt, st_, ixt,
            wimg + (size_t)lt0 * 8192, bl + (size_t)lt0 * HDIM,
            bn_g + (size_t)(l * 2 + 1) * HDIM, bn_b + (size_t)(l * 2 + 1) * HDIM,
            bn_m + (size_t)(l * 2 + 1) * HDIM, bn_v + (size_t)(l * 2 + 1) * HDIM,
            out_t, NTXN,
            aggu, su, ixu,
            wimg + (size_t)lt1 * 8192, bl + (size_t)lt1 * HDIM,
            bn_g + (size_t)(l * 2 + 0) * HDIM, bn_b + (size_t)(l * 2 + 0) * HDIM,
            bn_m + (size_t)(l * 2 + 0) * HDIM, bn_v + (size_t)(l * 2 + 0) * HDIM,
            out_u, NUSR);
    }

    // 3) MLP head (final layer wrote buffer index (NLAY-1)&1 = 0)
    mlp_mma<<<(NTOT + 255) / 256, 256>>>(hu[(NLAY - 1) & 1], ht[(NLAY - 1) & 1],
                                         w1img, b1, W2, b2, out);
}